// round 1
// baseline (speedup 1.0000x reference)
#include <cuda_runtime.h>

#define S_LEN 2048
#define DK 64
#define BM 128
#define BN 64
#define NBH 32                          // B*H = 2*16
#define QS_STRIDE 65                    // padded, scalar access
#define PS_STRIDE 68                    // padded, float4-aligned
#define CTX_ELEMS ((size_t)NBH * S_LEN * DK)   // 4194304

#define SMEM_FLOATS (BM*QS_STRIDE + BM*PS_STRIDE + DK*BN + BN*DK)
#define SMEM_BYTES  (SMEM_FLOATS * 4)

__device__ float g_lsum[NBH * S_LEN];

// ---------------------------------------------------------------------------
// Pass 1: fused QK^T -> exp -> (unnormalized attn write) -> PV, per 128-row
// q-block. Causal: only processes key tiles up to the diagonal.
// ---------------------------------------------------------------------------
__global__ __launch_bounds__(256, 2)
void attn_pass1(const float* __restrict__ Qg, const float* __restrict__ Kg,
                const float* __restrict__ Vg, float* __restrict__ out)
{
    extern __shared__ float sm[];
    float* Qs = sm;                       // [BM][QS_STRIDE]
    float* Ps = Qs + BM * QS_STRIDE;      // [BM][PS_STRIDE]
    float* Kt = Ps + BM * PS_STRIDE;      // [DK][BN]  (K transposed)
    float* Vs = Kt + DK * BN;             // [BN][DK]

    const int bh = blockIdx.y;
    const int qb = (int)gridDim.x - 1 - (int)blockIdx.x;  // heavy blocks first
    const int tid = threadIdx.x;
    const int tx = tid & 15;
    const int ty = tid >> 4;

    const float* Qbh = Qg + (size_t)bh * S_LEN * DK;
    const float* Kbh = Kg + (size_t)bh * S_LEN * DK;
    const float* Vbh = Vg + (size_t)bh * S_LEN * DK;
    float* ctx  = out + (size_t)bh * S_LEN * DK;
    float* attn = out + CTX_ELEMS + (size_t)bh * S_LEN * S_LEN;

    const int row0 = qb * BM;

    // Load Q tile (128x64) into padded smem
    for (int i = tid; i < BM * DK / 4; i += 256) {
        int r  = i >> 4;
        int d4 = (i & 15) << 2;
        float4 v = *(const float4*)(Qbh + (size_t)(row0 + r) * DK + d4);
        float* dst = Qs + r * QS_STRIDE + d4;
        dst[0] = v.x; dst[1] = v.y; dst[2] = v.z; dst[3] = v.w;
    }

    float o[8][4];
    float lpart[8];
    #pragma unroll
    for (int rr = 0; rr < 8; rr++) {
        lpart[rr] = 0.f;
        o[rr][0] = 0.f; o[rr][1] = 0.f; o[rr][2] = 0.f; o[rr][3] = 0.f;
    }

    const int nkb = 2 * qb + 2;   // key tiles up to & including diagonal
    for (int jb = 0; jb < nkb; jb++) {
        const int c0 = jb * BN;
        __syncthreads();   // prev iter done with Kt/Vs (and Qs visible, iter 0)

        // Load K^T (scatter) and V (copy) tiles
        for (int i = tid; i < BN * DK / 4; i += 256) {
            int c  = i >> 4;
            int d4 = (i & 15) << 2;
            float4 kv = *(const float4*)(Kbh + (size_t)(c0 + c) * DK + d4);
            Kt[(d4 + 0) * BN + c] = kv.x;
            Kt[(d4 + 1) * BN + c] = kv.y;
            Kt[(d4 + 2) * BN + c] = kv.z;
            Kt[(d4 + 3) * BN + c] = kv.w;
            float4 vv = *(const float4*)(Vbh + (size_t)(c0 + c) * DK + d4);
            *(float4*)(Vs + c * DK + d4) = vv;
        }
        __syncthreads();

        // S = Q @ K^T  (128x64 tile, 8x4 per thread)
        float acc[8][4];
        #pragma unroll
        for (int rr = 0; rr < 8; rr++) {
            acc[rr][0] = 0.f; acc[rr][1] = 0.f; acc[rr][2] = 0.f; acc[rr][3] = 0.f;
        }
        #pragma unroll 4
        for (int d = 0; d < DK; d++) {
            float4 kf = *(const float4*)(Kt + d * BN + (tx << 2));
            #pragma unroll
            for (int rr = 0; rr < 8; rr++) {
                float q = Qs[(rr * 16 + ty) * QS_STRIDE + d];
                acc[rr][0] += q * kf.x;
                acc[rr][1] += q * kf.y;
                acc[rr][2] += q * kf.z;
                acc[rr][3] += q * kf.w;
            }
        }

        // exp + causal mask + write unnormalized attn + stage P to smem
        #pragma unroll
        for (int rr = 0; rr < 8; rr++) {
            int r    = rr * 16 + ty;
            int grow = row0 + r;
            int gc   = c0 + (tx << 2);
            float4 p;
            p.x = (gc + 0 <= grow) ? __expf(acc[rr][0] * 0.125f) : 0.f;
            p.y = (gc + 1 <= grow) ? __expf(acc[rr][1] * 0.125f) : 0.f;
            p.z = (gc + 2 <= grow) ? __expf(acc[rr][2] * 0.125f) : 0.f;
            p.w = (gc + 3 <= grow) ? __expf(acc[rr][3] * 0.125f) : 0.f;
            lpart[rr] += p.x + p.y + p.z + p.w;
            *(float4*)(Ps + r * PS_STRIDE + (tx << 2)) = p;
            *(float4*)(attn + (size_t)grow * S_LEN + gc) = p;
        }
        __syncthreads();

        // O += P @ V  (k-dim = BN)
        #pragma unroll 4
        for (int c = 0; c < BN; c++) {
            float4 vf = *(const float4*)(Vs + c * DK + (tx << 2));
            #pragma unroll
            for (int rr = 0; rr < 8; rr++) {
                float p = Ps[(rr * 16 + ty) * PS_STRIDE + c];
                o[rr][0] += p * vf.x;
                o[rr][1] += p * vf.y;
                o[rr][2] += p * vf.z;
                o[rr][3] += p * vf.w;
            }
        }
    }

    // Reduce row sums across the 16 tx lanes (same warp half), normalize O.
    #pragma unroll
    for (int rr = 0; rr < 8; rr++) {
        float l = lpart[rr];
        l += __shfl_xor_sync(0xffffffffu, l, 1);
        l += __shfl_xor_sync(0xffffffffu, l, 2);
        l += __shfl_xor_sync(0xffffffffu, l, 4);
        l += __shfl_xor_sync(0xffffffffu, l, 8);
        int r    = rr * 16 + ty;
        int grow = row0 + r;
        if (tx == 0) g_lsum[bh * S_LEN + grow] = l;
        float inv = 1.f / l;
        float4 ov;
        ov.x = o[rr][0] * inv; ov.y = o[rr][1] * inv;
        ov.z = o[rr][2] * inv; ov.w = o[rr][3] * inv;
        *(float4*)(ctx + (size_t)grow * DK + (tx << 2)) = ov;
    }
}

// ---------------------------------------------------------------------------
// Pass 2: attn[row, col<=row] *= 1/l(row); attn[row, col>row] = 0.
// One block per global row (NBH*S_LEN rows), 256 threads, 2 float4 each.
// ---------------------------------------------------------------------------
__global__ __launch_bounds__(256)
void attn_pass2(float* __restrict__ out)
{
    const int gid = blockIdx.x;               // bh*S_LEN + row
    const int r   = gid & (S_LEN - 1);
    const float inv = 1.f / g_lsum[gid];
    float4* rowp = (float4*)(out + CTX_ELEMS + (size_t)gid * S_LEN);
    const int tid = threadIdx.x;

    #pragma unroll
    for (int it = 0; it < 2; it++) {
        int c4  = tid + it * 256;
        int col = c4 << 2;
        float4 v;
        if (col + 3 <= r) {                 // fully unmasked: scale
            v = rowp[c4];
            v.x *= inv; v.y *= inv; v.z *= inv; v.w *= inv;
        } else if (col > r) {               // fully masked: zero (no read)
            v.x = 0.f; v.y = 0.f; v.z = 0.f; v.w = 0.f;
        } else {                            // straddles diagonal
            v = rowp[c4];
            v.x = (col + 0 <= r) ? v.x * inv : 0.f;
            v.y = (col + 1 <= r) ? v.y * inv : 0.f;
            v.z = (col + 2 <= r) ? v.z * inv : 0.f;
            v.w = (col + 3 <= r) ? v.w * inv : 0.f;
        }
        rowp[c4] = v;
    }
}

extern "C" void kernel_launch(void* const* d_in, const int* in_sizes, int n_in,
                              void* d_out, int out_size)
{
    const float* Q = (const float*)d_in[0];
    const float* K = (const float*)d_in[1];
    const float* V = (const float*)d_in[2];
    float* out = (float*)d_out;

    cudaFuncSetAttribute(attn_pass1, cudaFuncAttributeMaxDynamicSharedMemorySize,
                         SMEM_BYTES);

    dim3 grid1(S_LEN / BM, NBH);
    attn_pass1<<<grid1, 256, SMEM_BYTES>>>(Q, K, V, out);
    attn_pass2<<<NBH * S_LEN, 256>>>(out);
}

// round 4
// speedup vs baseline: 1.9496x; 1.9496x over previous
#include <cuda_runtime.h>
#include <cstdint>

#define S_LEN 2048
#define DK 64
#define BM 128
#define BN 64
#define NBH 32
#define CTX_ELEMS ((size_t)NBH * S_LEN * DK)

#define RS 144   // smem row stride in bytes (72 bf16) -> conflict-free frags

#define OFF_QHI 0
#define OFF_QLO (BM * RS)
#define OFF_KHI (2 * BM * RS)
#define OFF_KLO (OFF_KHI + BN * RS)
#define OFF_VHI (OFF_KLO + BN * RS)
#define OFF_VLO (OFF_VHI + BN * RS)
#define SMEM_TOTAL (OFF_VLO + BN * RS)   // 73728 B

__device__ float g_lsum[NBH * S_LEN];

// ---------------------------------------------------------------------------
// helpers
// ---------------------------------------------------------------------------
__device__ __forceinline__ uint32_t smem_u32(const void* p) {
    uint32_t a;
    asm("{ .reg .u64 t; cvta.to.shared.u64 t, %1; cvt.u32.u64 %0, t; }"
        : "=r"(a) : "l"(p));
    return a;
}

__device__ __forceinline__ uint32_t lds32(uint32_t a) {
    uint32_t v;
    asm volatile("ld.shared.b32 %0, [%1];" : "=r"(v) : "r"(a));
    return v;
}

// pack two f32 -> bf16x2 (a -> low half, b -> high half)
__device__ __forceinline__ uint32_t bf2(float a, float b) {
    uint32_t r;
    asm("cvt.rn.bf16x2.f32 %0, %1, %2;" : "=r"(r) : "f"(b), "f"(a));
    return r;
}
__device__ __forceinline__ float bflo(uint32_t p) { return __uint_as_float(p << 16); }
__device__ __forceinline__ float bfhi(uint32_t p) { return __uint_as_float(p & 0xffff0000u); }

// m16n8k16 bf16 mma, D=C (accumulate in-place)
__device__ __forceinline__ void mma16816(float* c, const uint32_t* a, const uint32_t* b) {
    asm volatile(
        "mma.sync.aligned.m16n8k16.row.col.f32.bf16.bf16.f32 "
        "{%0,%1,%2,%3}, {%4,%5,%6,%7}, {%8,%9}, {%0,%1,%2,%3};"
        : "+f"(c[0]), "+f"(c[1]), "+f"(c[2]), "+f"(c[3])
        : "r"(a[0]), "r"(a[1]), "r"(a[2]), "r"(a[3]), "r"(b[0]), "r"(b[1]));
}

// convert 8 f32 -> hi/lo bf16 16B chunks, store linear (no swizzle)
__device__ __forceinline__ void cvt_store8(const float* x, char* hi_base,
                                           char* lo_base, uint32_t byte_off) {
    uint4 hi4, lo4;
    uint32_t* hp = (uint32_t*)&hi4;
    uint32_t* lp = (uint32_t*)&lo4;
    #pragma unroll
    for (int i = 0; i < 4; i++) {
        uint32_t h = bf2(x[2 * i], x[2 * i + 1]);
        hp[i] = h;
        lp[i] = bf2(x[2 * i] - bflo(h), x[2 * i + 1] - bfhi(h));
    }
    *(uint4*)(hi_base + byte_off) = hi4;
    *(uint4*)(lo_base + byte_off) = lo4;
}

// ---------------------------------------------------------------------------
// Pass 1: mma.sync flash attention; unnormalized attn + normalized context.
// CTA = 256 threads (8 warps), one (bh, 128-row q-block). Warp w owns rows
// [w*16, w*16+16) of the block and all 64 key columns of each tile.
// ---------------------------------------------------------------------------
__global__ __launch_bounds__(256)
void attn_pass1(const float* __restrict__ Qg, const float* __restrict__ Kg,
                const float* __restrict__ Vg, float* __restrict__ out)
{
    extern __shared__ char smc[];
    const uint32_t smb = smem_u32(smc);
    const int tid  = threadIdx.x;
    const int wid  = tid >> 5;
    const int lane = tid & 31;
    const int r    = lane >> 2;     // fragment row-in-group
    const int q    = lane & 3;      // fragment col-group

    const int bh   = blockIdx.y;
    const int qb   = (int)gridDim.x - 1 - (int)blockIdx.x;  // heavy blocks first
    const int row0 = qb * BM;
    const int mrow = wid * 16;

    const float* Qbh = Qg + (size_t)bh * S_LEN * DK;
    const float* Kbh = Kg + (size_t)bh * S_LEN * DK;
    const float* Vbh = Vg + (size_t)bh * S_LEN * DK;
    float* ctx  = out + (size_t)bh * S_LEN * DK;
    float* attn = out + CTX_ELEMS + (size_t)bh * S_LEN * S_LEN;

    // ---- convert Q tile (2 threads per row, 32 elems each) ----
    {
        int row = tid >> 1, half = tid & 1;
        const float* qrow = Qbh + (size_t)(row0 + row) * DK + half * 32;
        #pragma unroll
        for (int g = 0; g < 4; g++) {
            float4 a = __ldg((const float4*)(qrow + g * 8));
            float4 b = __ldg((const float4*)(qrow + g * 8 + 4));
            float x[8] = {a.x, a.y, a.z, a.w, b.x, b.y, b.z, b.w};
            cvt_store8(x, smc + OFF_QHI, smc + OFF_QLO,
                       (uint32_t)(row * RS + half * 64 + g * 16));
        }
    }

    float oacc[8][4];
    #pragma unroll
    for (int j = 0; j < 8; j++) {
        oacc[j][0] = 0.f; oacc[j][1] = 0.f; oacc[j][2] = 0.f; oacc[j][3] = 0.f;
    }
    float lsum0 = 0.f, lsum1 = 0.f;
    const int grow0 = row0 + mrow + r;          // this thread's first row
    const int rowmax = row0 + mrow + 15;        // warp band's last row

    const int nkb = 2 * qb + 2;
    for (int jb = 0; jb < nkb; jb++) {
        const int c0 = jb * BN;
        if (jb) __syncthreads();                // prior PV done with K/V smem

        // ---- convert K tile (4 threads per key row, 16 elems each) ----
        {
            int row = tid >> 2, qt = tid & 3;
            const float* krow = Kbh + (size_t)(c0 + row) * DK + qt * 16;
            #pragma unroll
            for (int g = 0; g < 2; g++) {
                float4 a = __ldg((const float4*)(krow + g * 8));
                float4 b = __ldg((const float4*)(krow + g * 8 + 4));
                float x[8] = {a.x, a.y, a.z, a.w, b.x, b.y, b.z, b.w};
                cvt_store8(x, smc + OFF_KHI, smc + OFF_KLO,
                           (uint32_t)(row * RS + (qt * 16 + g * 8) * 2));
            }
        }
        // ---- convert V transposed: Vt[d][key] ----
        {
            int d = tid >> 2, qt = tid & 3;
            #pragma unroll
            for (int g = 0; g < 2; g++) {
                int k0 = qt * 16 + g * 8;
                float x[8];
                #pragma unroll
                for (int j = 0; j < 8; j++)
                    x[j] = __ldg(Vbh + (size_t)(c0 + k0 + j) * DK + d);
                cvt_store8(x, smc + OFF_VHI, smc + OFF_VLO,
                           (uint32_t)(d * RS + k0 * 2));
            }
        }
        __syncthreads();

        if (c0 > rowmax) continue;              // tile fully masked for warp

        // ---- S = Q @ K^T (split-bf16, 3 terms, shared frag loads) ----
        float sacc[8][4];
        #pragma unroll
        for (int j = 0; j < 8; j++) {
            sacc[j][0] = 0.f; sacc[j][1] = 0.f; sacc[j][2] = 0.f; sacc[j][3] = 0.f;
        }
        #pragma unroll
        for (int ks = 0; ks < 4; ks++) {
            uint32_t ah[4], al[4];
            uint32_t aoff = (uint32_t)((mrow + r) * RS + ks * 32 + q * 4);
            ah[0] = lds32(smb + OFF_QHI + aoff);
            ah[1] = lds32(smb + OFF_QHI + aoff + 8 * RS);
            ah[2] = lds32(smb + OFF_QHI + aoff + 16);
            ah[3] = lds32(smb + OFF_QHI + aoff + 8 * RS + 16);
            al[0] = lds32(smb + OFF_QLO + aoff);
            al[1] = lds32(smb + OFF_QLO + aoff + 8 * RS);
            al[2] = lds32(smb + OFF_QLO + aoff + 16);
            al[3] = lds32(smb + OFF_QLO + aoff + 8 * RS + 16);
            #pragma unroll
            for (int j = 0; j < 8; j++) {
                uint32_t boff = (uint32_t)((j * 8 + r) * RS + ks * 32 + q * 4);
                uint32_t bh2[2], bl2[2];
                bh2[0] = lds32(smb + OFF_KHI + boff);
                bh2[1] = lds32(smb + OFF_KHI + boff + 16);
                bl2[0] = lds32(smb + OFF_KLO + boff);
                bl2[1] = lds32(smb + OFF_KLO + boff + 16);
                mma16816(sacc[j], ah, bh2);
                mma16816(sacc[j], ah, bl2);
                mma16816(sacc[j], al, bh2);
            }
        }

        // ---- epilogue: exp + mask + attn write + P split to registers ----
        uint32_t phi[8][2], plo[8][2];
        #pragma unroll
        for (int j = 0; j < 8; j++) {
            int cj = c0 + j * 8 + q * 2;
            float p0 = (cj     <= grow0)     ? __expf(sacc[j][0] * 0.125f) : 0.f;
            float p1 = (cj + 1 <= grow0)     ? __expf(sacc[j][1] * 0.125f) : 0.f;
            float p2 = (cj     <= grow0 + 8) ? __expf(sacc[j][2] * 0.125f) : 0.f;
            float p3 = (cj + 1 <= grow0 + 8) ? __expf(sacc[j][3] * 0.125f) : 0.f;
            lsum0 += p0 + p1;
            lsum1 += p2 + p3;
            *(float2*)(attn + (size_t)grow0 * S_LEN + cj)       = make_float2(p0, p1);
            *(float2*)(attn + (size_t)(grow0 + 8) * S_LEN + cj) = make_float2(p2, p3);
            uint32_t h0 = bf2(p0, p1), h1 = bf2(p2, p3);
            phi[j][0] = h0; phi[j][1] = h1;
            plo[j][0] = bf2(p0 - bflo(h0), p1 - bfhi(h0));
            plo[j][1] = bf2(p2 - bflo(h1), p3 - bfhi(h1));
        }

        // ---- O += P @ V (A from registers, split-bf16) ----
        #pragma unroll
        for (int ks = 0; ks < 4; ks++) {
            uint32_t ah[4] = {phi[2 * ks][0], phi[2 * ks][1],
                              phi[2 * ks + 1][0], phi[2 * ks + 1][1]};
            uint32_t al[4] = {plo[2 * ks][0], plo[2 * ks][1],
                              plo[2 * ks + 1][0], plo[2 * ks + 1][1]};
            #pragma unroll
            for (int j = 0; j < 8; j++) {
                uint32_t boff = (uint32_t)((j * 8 + r) * RS + ks * 32 + q * 4);
                uint32_t vh[2], vl[2];
                vh[0] = lds32(smb + OFF_VHI + boff);
                vh[1] = lds32(smb + OFF_VHI + boff + 16);
                vl[0] = lds32(smb + OFF_VLO + boff);
                vl[1] = lds32(smb + OFF_VLO + boff + 16);
                mma16816(oacc[j], ah, vh);
                mma16816(oacc[j], ah, vl);
                mma16816(oacc[j], al, vh);
            }
        }
    }

    // ---- reduce row sums within quads, normalize O, write context ----
    lsum0 += __shfl_xor_sync(0xffffffffu, lsum0, 1);
    lsum0 += __shfl_xor_sync(0xffffffffu, lsum0, 2);
    lsum1 += __shfl_xor_sync(0xffffffffu, lsum1, 1);
    lsum1 += __shfl_xor_sync(0xffffffffu, lsum1, 2);
    if (q == 0) {
        g_lsum[bh * S_LEN + grow0]     = lsum0;
        g_lsum[bh * S_LEN + grow0 + 8] = lsum1;
    }
    const float inv0 = 1.f / lsum0;
    const float inv1 = 1.f / lsum1;
    #pragma unroll
    for (int j = 0; j < 8; j++) {
        int cj = j * 8 + q * 2;
        *(float2*)(ctx + (size_t)grow0 * DK + cj) =
            make_float2(oacc[j][0] * inv0, oacc[j][1] * inv0);
        *(float2*)(ctx + (size_t)(grow0 + 8) * DK + cj) =
            make_float2(oacc[j][2] * inv1, oacc[j][3] * inv1);
    }
}

// ---------------------------------------------------------------------------
// Pass 2: attn[row, col<=row] *= 1/l(row); attn[row, col>row] = 0.
// ---------------------------------------------------------------------------
__global__ __launch_bounds__(256)
void attn_pass2(float* __restrict__ out)
{
    const int gid = blockIdx.x;               // bh*S_LEN + row
    const int r   = gid & (S_LEN - 1);
    const float inv = 1.f / g_lsum[gid];
    float4* rowp = (float4*)(out + CTX_ELEMS + (size_t)gid * S_LEN);
    const int tid = threadIdx.x;

    #pragma unroll
    for (int it = 0; it < 2; it++) {
        int c4  = tid + it * 256;
        int col = c4 << 2;
        float4 v;
        if (col + 3 <= r) {
            v = rowp[c4];
            v.x *= inv; v.y *= inv; v.z *= inv; v.w *= inv;
        } else if (col > r) {
            v.x = 0.f; v.y = 0.f; v.z = 0.f; v.w = 0.f;
        } else {
            v = rowp[c4];
            v.x = (col + 0 <= r) ? v.x * inv : 0.f;
            v.y = (col + 1 <= r) ? v.y * inv : 0.f;
            v.z = (col + 2 <= r) ? v.z * inv : 0.f;
            v.w = (col + 3 <= r) ? v.w * inv : 0.f;
        }
        rowp[c4] = v;
    }
}

extern "C" void kernel_launch(void* const* d_in, const int* in_sizes, int n_in,
                              void* d_out, int out_size)
{
    const float* Q = (const float*)d_in[0];
    const float* K = (const float*)d_in[1];
    const float* V = (const float*)d_in[2];
    float* out = (float*)d_out;

    cudaFuncSetAttribute(attn_pass1, cudaFuncAttributeMaxDynamicSharedMemorySize,
                         SMEM_TOTAL);

    dim3 grid1(S_LEN / BM, NBH);
    attn_pass1<<<grid1, 256, SMEM_TOTAL>>>(Q, K, V, out);
    attn_pass2<<<NBH * S_LEN, 256>>>(out);
}

// round 5
// speedup vs baseline: 1.9661x; 1.0085x over previous
#include <cuda_runtime.h>
#include <cstdint>

#define S_LEN 2048
#define DK 64
#define BM 128
#define BN 64
#define NBH 32
#define CTX_ELEMS ((size_t)NBH * S_LEN * DK)

#define RS 144   // smem row stride in bytes (72 bf16) -> conflict-free frags

#define OFF_QHI 0
#define OFF_QLO (BM * RS)
#define OFF_KHI (2 * BM * RS)
#define OFF_KLO (OFF_KHI + BN * RS)
#define OFF_VHI (OFF_KLO + BN * RS)
#define OFF_VLO (OFF_VHI + BN * RS)
#define SMEM_TOTAL (OFF_VLO + BN * RS)   // 73728 B

__device__ float g_lsum[NBH * S_LEN];

// ---------------------------------------------------------------------------
// helpers
// ---------------------------------------------------------------------------
__device__ __forceinline__ uint32_t smem_u32(const void* p) {
    uint32_t a;
    asm("{ .reg .u64 t; cvta.to.shared.u64 t, %1; cvt.u32.u64 %0, t; }"
        : "=r"(a) : "l"(p));
    return a;
}

__device__ __forceinline__ uint32_t lds32(uint32_t a) {
    uint32_t v;
    asm volatile("ld.shared.b32 %0, [%1];" : "=r"(v) : "r"(a));
    return v;
}

// pack two f32 -> bf16x2 (a -> low half, b -> high half)
__device__ __forceinline__ uint32_t bf2(float a, float b) {
    uint32_t r;
    asm("cvt.rn.bf16x2.f32 %0, %1, %2;" : "=r"(r) : "f"(b), "f"(a));
    return r;
}
__device__ __forceinline__ float bflo(uint32_t p) { return __uint_as_float(p << 16); }
__device__ __forceinline__ float bfhi(uint32_t p) { return __uint_as_float(p & 0xffff0000u); }

// m16n8k16 bf16 mma, D=C (accumulate in-place)
__device__ __forceinline__ void mma16816(float* c, const uint32_t* a, const uint32_t* b) {
    asm volatile(
        "mma.sync.aligned.m16n8k16.row.col.f32.bf16.bf16.f32 "
        "{%0,%1,%2,%3}, {%4,%5,%6,%7}, {%8,%9}, {%0,%1,%2,%3};"
        : "+f"(c[0]), "+f"(c[1]), "+f"(c[2]), "+f"(c[3])
        : "r"(a[0]), "r"(a[1]), "r"(a[2]), "r"(a[3]), "r"(b[0]), "r"(b[1]));
}

// convert 8 f32 -> hi/lo bf16 16B chunks, store linear (no swizzle)
__device__ __forceinline__ void cvt_store8(const float* x, char* hi_base,
                                           char* lo_base, uint32_t byte_off) {
    uint4 hi4, lo4;
    uint32_t* hp = (uint32_t*)&hi4;
    uint32_t* lp = (uint32_t*)&lo4;
    #pragma unroll
    for (int i = 0; i < 4; i++) {
        uint32_t h = bf2(x[2 * i], x[2 * i + 1]);
        hp[i] = h;
        lp[i] = bf2(x[2 * i] - bflo(h), x[2 * i + 1] - bfhi(h));
    }
    *(uint4*)(hi_base + byte_off) = hi4;
    *(uint4*)(lo_base + byte_off) = lo4;
}

// ---------------------------------------------------------------------------
// Pass 1: mma.sync flash attention; unnormalized attn + normalized context.
// CTA = 256 threads (8 warps), one (bh, 128-row q-block). Warp w owns rows
// [w*16, w*16+16) of the block and all 64 key columns of each tile.
// ---------------------------------------------------------------------------
__global__ __launch_bounds__(256)
void attn_pass1(const float* __restrict__ Qg, const float* __restrict__ Kg,
                const float* __restrict__ Vg, float* __restrict__ out)
{
    extern __shared__ char smc[];
    const uint32_t smb = smem_u32(smc);
    const int tid  = threadIdx.x;
    const int wid  = tid >> 5;
    const int lane = tid & 31;
    const int r    = lane >> 2;     // fragment row-in-group
    const int q    = lane & 3;      // fragment col-group

    const int bh   = blockIdx.y;
    const int qb   = (int)gridDim.x - 1 - (int)blockIdx.x;  // heavy blocks first
    const int row0 = qb * BM;
    const int mrow = wid * 16;

    const float* Qbh = Qg + (size_t)bh * S_LEN * DK;
    const float* Kbh = Kg + (size_t)bh * S_LEN * DK;
    const float* Vbh = Vg + (size_t)bh * S_LEN * DK;
    float* ctx  = out + (size_t)bh * S_LEN * DK;
    float* attn = out + CTX_ELEMS + (size_t)bh * S_LEN * S_LEN;

    // ---- convert Q tile (2 threads per row, 32 elems each) ----
    {
        int row = tid >> 1, half = tid & 1;
        const float* qrow = Qbh + (size_t)(row0 + row) * DK + half * 32;
        #pragma unroll
        for (int g = 0; g < 4; g++) {
            float4 a = __ldg((const float4*)(qrow + g * 8));
            float4 b = __ldg((const float4*)(qrow + g * 8 + 4));
            float x[8] = {a.x, a.y, a.z, a.w, b.x, b.y, b.z, b.w};
            cvt_store8(x, smc + OFF_QHI, smc + OFF_QLO,
                       (uint32_t)(row * RS + half * 64 + g * 16));
        }
    }

    float oacc[8][4];
    #pragma unroll
    for (int j = 0; j < 8; j++) {
        oacc[j][0] = 0.f; oacc[j][1] = 0.f; oacc[j][2] = 0.f; oacc[j][3] = 0.f;
    }
    float lsum0 = 0.f, lsum1 = 0.f;
    const int grow0 = row0 + mrow + r;          // this thread's first row
    const int rowmax = row0 + mrow + 15;        // warp band's last row

    const int nkb = 2 * qb + 2;
    for (int jb = 0; jb < nkb; jb++) {
        const int c0 = jb * BN;
        if (jb) __syncthreads();                // prior PV done with K/V smem

        // ---- convert K tile (4 threads per key row, 16 elems each) ----
        {
            int row = tid >> 2, qt = tid & 3;
            const float* krow = Kbh + (size_t)(c0 + row) * DK + qt * 16;
            #pragma unroll
            for (int g = 0; g < 2; g++) {
                float4 a = __ldg((const float4*)(krow + g * 8));
                float4 b = __ldg((const float4*)(krow + g * 8 + 4));
                float x[8] = {a.x, a.y, a.z, a.w, b.x, b.y, b.z, b.w};
                cvt_store8(x, smc + OFF_KHI, smc + OFF_KLO,
                           (uint32_t)(row * RS + (qt * 16 + g * 8) * 2));
            }
        }
        // ---- convert V transposed: Vt[d][key] ----
        {
            int d = tid >> 2, qt = tid & 3;
            #pragma unroll
            for (int g = 0; g < 2; g++) {
                int k0 = qt * 16 + g * 8;
                float x[8];
                #pragma unroll
                for (int j = 0; j < 8; j++)
                    x[j] = __ldg(Vbh + (size_t)(c0 + k0 + j) * DK + d);
                cvt_store8(x, smc + OFF_VHI, smc + OFF_VLO,
                           (uint32_t)(d * RS + k0 * 2));
            }
        }
        __syncthreads();

        if (c0 > rowmax) continue;              // tile fully masked for warp

        // ---- S = Q @ K^T (split-bf16, 3 terms, shared frag loads) ----
        float sacc[8][4];
        #pragma unroll
        for (int j = 0; j < 8; j++) {
            sacc[j][0] = 0.f; sacc[j][1] = 0.f; sacc[j][2] = 0.f; sacc[j][3] = 0.f;
        }
        #pragma unroll
        for (int ks = 0; ks < 4; ks++) {
            uint32_t ah[4], al[4];
            uint32_t aoff = (uint32_t)((mrow + r) * RS + ks * 32 + q * 4);
            ah[0] = lds32(smb + OFF_QHI + aoff);
            ah[1] = lds32(smb + OFF_QHI + aoff + 8 * RS);
            ah[2] = lds32(smb + OFF_QHI + aoff + 16);
            ah[3] = lds32(smb + OFF_QHI + aoff + 8 * RS + 16);
            al[0] = lds32(smb + OFF_QLO + aoff);
            al[1] = lds32(smb + OFF_QLO + aoff + 8 * RS);
            al[2] = lds32(smb + OFF_QLO + aoff + 16);
            al[3] = lds32(smb + OFF_QLO + aoff + 8 * RS + 16);
            #pragma unroll
            for (int j = 0; j < 8; j++) {
                uint32_t boff = (uint32_t)((j * 8 + r) * RS + ks * 32 + q * 4);
                uint32_t bh2[2], bl2[2];
                bh2[0] = lds32(smb + OFF_KHI + boff);
                bh2[1] = lds32(smb + OFF_KHI + boff + 16);
                bl2[0] = lds32(smb + OFF_KLO + boff);
                bl2[1] = lds32(smb + OFF_KLO + boff + 16);
                mma16816(sacc[j], ah, bh2);
                mma16816(sacc[j], ah, bl2);
                mma16816(sacc[j], al, bh2);
            }
        }

        // ---- epilogue: exp + mask + attn write + P split to registers ----
        uint32_t phi[8][2], plo[8][2];
        #pragma unroll
        for (int j = 0; j < 8; j++) {
            int cj = c0 + j * 8 + q * 2;
            float p0 = (cj     <= grow0)     ? __expf(sacc[j][0] * 0.125f) : 0.f;
            float p1 = (cj + 1 <= grow0)     ? __expf(sacc[j][1] * 0.125f) : 0.f;
            float p2 = (cj     <= grow0 + 8) ? __expf(sacc[j][2] * 0.125f) : 0.f;
            float p3 = (cj + 1 <= grow0 + 8) ? __expf(sacc[j][3] * 0.125f) : 0.f;
            lsum0 += p0 + p1;
            lsum1 += p2 + p3;
            *(float2*)(attn + (size_t)grow0 * S_LEN + cj)       = make_float2(p0, p1);
            *(float2*)(attn + (size_t)(grow0 + 8) * S_LEN + cj) = make_float2(p2, p3);
            uint32_t h0 = bf2(p0, p1), h1 = bf2(p2, p3);
            phi[j][0] = h0; phi[j][1] = h1;
            plo[j][0] = bf2(p0 - bflo(h0), p1 - bfhi(h0));
            plo[j][1] = bf2(p2 - bflo(h1), p3 - bfhi(h1));
        }

        // ---- O += P @ V (A from registers, split-bf16) ----
        #pragma unroll
        for (int ks = 0; ks < 4; ks++) {
            uint32_t ah[4] = {phi[2 * ks][0], phi[2 * ks][1],
                              phi[2 * ks + 1][0], phi[2 * ks + 1][1]};
            uint32_t al[4] = {plo[2 * ks][0], plo[2 * ks][1],
                              plo[2 * ks + 1][0], plo[2 * ks + 1][1]};
            #pragma unroll
            for (int j = 0; j < 8; j++) {
                uint32_t boff = (uint32_t)((j * 8 + r) * RS + ks * 32 + q * 4);
                uint32_t vh[2], vl[2];
                vh[0] = lds32(smb + OFF_VHI + boff);
                vh[1] = lds32(smb + OFF_VHI + boff + 16);
                vl[0] = lds32(smb + OFF_VLO + boff);
                vl[1] = lds32(smb + OFF_VLO + boff + 16);
                mma16816(oacc[j], ah, vh);
                mma16816(oacc[j], ah, vl);
                mma16816(oacc[j], al, vh);
            }
        }
    }

    // ---- reduce row sums within quads, normalize O, write context ----
    lsum0 += __shfl_xor_sync(0xffffffffu, lsum0, 1);
    lsum0 += __shfl_xor_sync(0xffffffffu, lsum0, 2);
    lsum1 += __shfl_xor_sync(0xffffffffu, lsum1, 1);
    lsum1 += __shfl_xor_sync(0xffffffffu, lsum1, 2);
    if (q == 0) {
        g_lsum[bh * S_LEN + grow0]     = lsum0;
        g_lsum[bh * S_LEN + grow0 + 8] = lsum1;
    }
    const float inv0 = 1.f / lsum0;
    const float inv1 = 1.f / lsum1;
    #pragma unroll
    for (int j = 0; j < 8; j++) {
        int cj = j * 8 + q * 2;
        *(float2*)(ctx + (size_t)grow0 * DK + cj) =
            make_float2(oacc[j][0] * inv0, oacc[j][1] * inv0);
        *(float2*)(ctx + (size_t)(grow0 + 8) * DK + cj) =
            make_float2(oacc[j][2] * inv1, oacc[j][3] * inv1);
    }
}

// ---------------------------------------------------------------------------
// Pass 2: attn[row, col<=row] *= 1/l(row); attn[row, col>row] = 0.
// ---------------------------------------------------------------------------
__global__ __launch_bounds__(256)
void attn_pass2(float* __restrict__ out)
{
    const int gid = blockIdx.x;               // bh*S_LEN + row
    const int r   = gid & (S_LEN - 1);
    const float inv = 1.f / g_lsum[gid];
    float4* rowp = (float4*)(out + CTX_ELEMS + (size_t)gid * S_LEN);
    const int tid = threadIdx.x;

    #pragma unroll
    for (int it = 0; it < 2; it++) {
        int c4  = tid + it * 256;
        int col = c4 << 2;
        float4 v;
        if (col + 3 <= r) {
            v = rowp[c4];
            v.x *= inv; v.y *= inv; v.z *= inv; v.w *= inv;
        } else if (col > r) {
            v.x = 0.f; v.y = 0.f; v.z = 0.f; v.w = 0.f;
        } else {
            v = rowp[c4];
            v.x = (col + 0 <= r) ? v.x * inv : 0.f;
            v.y = (col + 1 <= r) ? v.y * inv : 0.f;
            v.z = (col + 2 <= r) ? v.z * inv : 0.f;
            v.w = (col + 3 <= r) ? v.w * inv : 0.f;
        }
        rowp[c4] = v;
    }
}

extern "C" void kernel_launch(void* const* d_in, const int* in_sizes, int n_in,
                              void* d_out, int out_size)
{
    const float* Q = (const float*)d_in[0];
    const float* K = (const float*)d_in[1];
    const float* V = (const float*)d_in[2];
    float* out = (float*)d_out;

    cudaFuncSetAttribute(attn_pass1, cudaFuncAttributeMaxDynamicSharedMemorySize,
                         SMEM_TOTAL);

    dim3 grid1(S_LEN / BM, NBH);
    attn_pass1<<<grid1, 256, SMEM_TOTAL>>>(Q, K, V, out);
    attn_pass2<<<NBH * S_LEN, 256>>>(out);
}

// round 7
// speedup vs baseline: 2.0835x; 1.0597x over previous
#include <cuda_runtime.h>
#include <cstdint>

#define S_LEN 2048
#define DK 64
#define BM 128
#define BN 64
#define NBH 32
#define CTX_ELEMS ((size_t)NBH * S_LEN * DK)

#define RS 144   // smem row stride in bytes -> conflict-free LDSM

#define OFF_QHI 0
#define OFF_QLO (BM * RS)
#define OFF_KHI (2 * BM * RS)
#define OFF_KLO (OFF_KHI + BN * RS)
#define OFF_VHI (OFF_KLO + BN * RS)
#define OFF_VLO (OFF_VHI + BN * RS)
#define SMEM_TOTAL (OFF_VLO + BN * RS)   // 73728 B -> 2 CTAs/SM

__device__ float g_lsum[NBH * S_LEN];

// ---------------------------------------------------------------------------
// helpers
// ---------------------------------------------------------------------------
__device__ __forceinline__ uint32_t smem_u32(const void* p) {
    uint32_t a;
    asm("{ .reg .u64 t; cvta.to.shared.u64 t, %1; cvt.u32.u64 %0, t; }"
        : "=r"(a) : "l"(p));
    return a;
}

__device__ __forceinline__ void ldsm_x4(uint32_t* r, uint32_t addr) {
    asm volatile("ldmatrix.sync.aligned.m8n8.x4.shared.b16 {%0,%1,%2,%3}, [%4];"
        : "=r"(r[0]), "=r"(r[1]), "=r"(r[2]), "=r"(r[3]) : "r"(addr));
}
__device__ __forceinline__ void ldsm_x4t(uint32_t* r, uint32_t addr) {
    asm volatile("ldmatrix.sync.aligned.m8n8.x4.trans.shared.b16 {%0,%1,%2,%3}, [%4];"
        : "=r"(r[0]), "=r"(r[1]), "=r"(r[2]), "=r"(r[3]) : "r"(addr));
}

// pack two f32 -> bf16x2 (a -> low half, b -> high half)
__device__ __forceinline__ uint32_t bf2(float a, float b) {
    uint32_t r;
    asm("cvt.rn.bf16x2.f32 %0, %1, %2;" : "=r"(r) : "f"(b), "f"(a));
    return r;
}
__device__ __forceinline__ float bflo(uint32_t p) { return __uint_as_float(p << 16); }
__device__ __forceinline__ float bfhi(uint32_t p) { return __uint_as_float(p & 0xffff0000u); }

// m16n8k16 bf16 mma, D=C (accumulate in-place)
__device__ __forceinline__ void mma16816(float* c, const uint32_t* a, const uint32_t* b) {
    asm volatile(
        "mma.sync.aligned.m16n8k16.row.col.f32.bf16.bf16.f32 "
        "{%0,%1,%2,%3}, {%4,%5,%6,%7}, {%8,%9}, {%0,%1,%2,%3};"
        : "+f"(c[0]), "+f"(c[1]), "+f"(c[2]), "+f"(c[3])
        : "r"(a[0]), "r"(a[1]), "r"(a[2]), "r"(a[3]), "r"(b[0]), "r"(b[1]));
}

// convert 8 f32 (two float4) -> hi/lo bf16 16B chunks, store linear
__device__ __forceinline__ void cvt_store8(float4 a, float4 b, char* hi_base,
                                           char* lo_base, uint32_t byte_off) {
    float x[8] = {a.x, a.y, a.z, a.w, b.x, b.y, b.z, b.w};
    uint4 hi4, lo4;
    uint32_t* hp = (uint32_t*)&hi4;
    uint32_t* lp = (uint32_t*)&lo4;
    #pragma unroll
    for (int i = 0; i < 4; i++) {
        uint32_t h = bf2(x[2 * i], x[2 * i + 1]);
        hp[i] = h;
        lp[i] = bf2(x[2 * i] - bflo(h), x[2 * i + 1] - bfhi(h));
    }
    *(uint4*)(hi_base + byte_off) = hi4;
    *(uint4*)(lo_base + byte_off) = lo4;
}

// ---------------------------------------------------------------------------
// Pass 1: mma.sync flash attention; unnormalized attn + normalized context.
// CTA = 256 threads (8 warps), one (bh, 128-row q-block). Warp w owns rows
// [w*16, w*16+16) of the block and all 64 key columns of each tile.
// ---------------------------------------------------------------------------
__global__ __launch_bounds__(256, 2)
void attn_pass1(const float* __restrict__ Qg, const float* __restrict__ Kg,
                const float* __restrict__ Vg, float* __restrict__ out)
{
    extern __shared__ char smc[];
    const uint32_t smb = smem_u32(smc);
    const int tid  = threadIdx.x;
    const int wid  = tid >> 5;
    const int lane = tid & 31;
    const int r    = lane >> 2;     // C/A fragment row-in-group
    const int q    = lane & 3;      // fragment col-group

    const int bh   = blockIdx.y;
    const int qb   = (int)gridDim.x - 1 - (int)blockIdx.x;  // heavy blocks first
    const int row0 = qb * BM;
    const int mrow = wid * 16;

    const float* Qbh = Qg + (size_t)bh * S_LEN * DK;
    const float* Kbh = Kg + (size_t)bh * S_LEN * DK;
    const float* Vbh = Vg + (size_t)bh * S_LEN * DK;
    float* ctx  = out + (size_t)bh * S_LEN * DK;
    float* attn = out + CTX_ELEMS + (size_t)bh * S_LEN * S_LEN;

    // per-lane ldmatrix base offsets
    const uint32_t aQbase = (uint32_t)((mrow + (lane & 15)) * RS + (lane >> 4) * 16);
    const uint32_t bKbase = (uint32_t)(((lane >> 4) * 8 + (lane & 7)) * RS
                                       + ((lane >> 3) & 1) * 16);
    const uint32_t bVbase = (uint32_t)((((lane >> 3) & 1) * 8 + (lane & 7)) * RS
                                       + (lane >> 4) * 16);

    // ---- convert Q tile (2 threads per row, 32 elems each) ----
    {
        int row = tid >> 1, half = tid & 1;
        const float* qrow = Qbh + (size_t)(row0 + row) * DK + half * 32;
        #pragma unroll
        for (int g = 0; g < 4; g++) {
            float4 a = __ldg((const float4*)(qrow + g * 8));
            float4 b = __ldg((const float4*)(qrow + g * 8 + 4));
            cvt_store8(a, b, smc + OFF_QHI, smc + OFF_QLO,
                       (uint32_t)(row * RS + half * 64 + g * 16));
        }
    }

    float oacc[8][4];
    #pragma unroll
    for (int j = 0; j < 8; j++) {
        oacc[j][0] = 0.f; oacc[j][1] = 0.f; oacc[j][2] = 0.f; oacc[j][3] = 0.f;
    }
    float lsum0 = 0.f, lsum1 = 0.f;
    const int grow0  = row0 + mrow + r;         // this thread's first row
    const int rowmax = row0 + mrow + 15;        // warp band's last row

    // K/V gmem positions for this thread (4 threads per row, 16 floats each)
    const int ld_row = tid >> 2;
    const int ld_qt  = tid & 3;

    const int nkb = 2 * qb + 2;
    for (int jb = 0; jb < nkb; jb++) {
        const int c0 = jb * BN;

        // ---- issue gmem loads BEFORE the barrier (latency overlap) ----
        const float* krow = Kbh + (size_t)(c0 + ld_row) * DK + ld_qt * 16;
        const float* vrow = Vbh + (size_t)(c0 + ld_row) * DK + ld_qt * 16;
        float4 k0 = __ldg((const float4*)(krow));
        float4 k1 = __ldg((const float4*)(krow + 4));
        float4 k2 = __ldg((const float4*)(krow + 8));
        float4 k3 = __ldg((const float4*)(krow + 12));
        float4 v0 = __ldg((const float4*)(vrow));
        float4 v1 = __ldg((const float4*)(vrow + 4));
        float4 v2 = __ldg((const float4*)(vrow + 8));
        float4 v3 = __ldg((const float4*)(vrow + 12));

        if (jb) __syncthreads();                // prior tile done with K/V smem

        {
            uint32_t off = (uint32_t)(ld_row * RS + ld_qt * 32);
            cvt_store8(k0, k1, smc + OFF_KHI, smc + OFF_KLO, off);
            cvt_store8(k2, k3, smc + OFF_KHI, smc + OFF_KLO, off + 16);
            cvt_store8(v0, v1, smc + OFF_VHI, smc + OFF_VLO, off);
            cvt_store8(v2, v3, smc + OFF_VHI, smc + OFF_VLO, off + 16);
        }
        __syncthreads();

        if (c0 > rowmax) continue;              // tile fully masked for warp

        // ---- S = Q @ K^T (split-bf16, 3 terms) ----
        float sacc[8][4];
        #pragma unroll
        for (int j = 0; j < 8; j++) {
            sacc[j][0] = 0.f; sacc[j][1] = 0.f; sacc[j][2] = 0.f; sacc[j][3] = 0.f;
        }
        #pragma unroll
        for (int ks = 0; ks < 4; ks++) {
            uint32_t ah[4], al[4];
            ldsm_x4(ah, smb + OFF_QHI + aQbase + ks * 32);
            ldsm_x4(al, smb + OFF_QLO + aQbase + ks * 32);
            #pragma unroll
            for (int jp = 0; jp < 4; jp++) {
                uint32_t kh[4], kl[4];
                uint32_t boff = bKbase + (uint32_t)(jp * 16 * RS + ks * 32);
                ldsm_x4(kh, smb + OFF_KHI + boff);
                ldsm_x4(kl, smb + OFF_KLO + boff);
                mma16816(sacc[2 * jp],     ah, kh);
                mma16816(sacc[2 * jp + 1], ah, kh + 2);
                mma16816(sacc[2 * jp],     ah, kl);
                mma16816(sacc[2 * jp + 1], ah, kl + 2);
                mma16816(sacc[2 * jp],     al, kh);
                mma16816(sacc[2 * jp + 1], al, kh + 2);
            }
        }

        // ---- epilogue: exp + mask + attn write + P split to registers ----
        uint32_t phi[8][2], plo[8][2];
        #pragma unroll
        for (int j = 0; j < 8; j++) {
            int cj = c0 + j * 8 + q * 2;
            float p0 = (cj     <= grow0)     ? __expf(sacc[j][0] * 0.125f) : 0.f;
            float p1 = (cj + 1 <= grow0)     ? __expf(sacc[j][1] * 0.125f) : 0.f;
            float p2 = (cj     <= grow0 + 8) ? __expf(sacc[j][2] * 0.125f) : 0.f;
            float p3 = (cj + 1 <= grow0 + 8) ? __expf(sacc[j][3] * 0.125f) : 0.f;
            lsum0 += p0 + p1;
            lsum1 += p2 + p3;
            *(float2*)(attn + (size_t)grow0 * S_LEN + cj)       = make_float2(p0, p1);
            *(float2*)(attn + (size_t)(grow0 + 8) * S_LEN + cj) = make_float2(p2, p3);
            uint32_t h0 = bf2(p0, p1), h1 = bf2(p2, p3);
            phi[j][0] = h0; phi[j][1] = h1;
            plo[j][0] = bf2(p0 - bflo(h0), p1 - bfhi(h0));
            plo[j][1] = bf2(p2 - bflo(h1), p3 - bfhi(h1));
        }

        // ---- O += P @ V (A from registers, B via ldmatrix.trans) ----
        #pragma unroll
        for (int ks = 0; ks < 4; ks++) {
            uint32_t ah[4] = {phi[2 * ks][0], phi[2 * ks][1],
                              phi[2 * ks + 1][0], phi[2 * ks + 1][1]};
            uint32_t al[4] = {plo[2 * ks][0], plo[2 * ks][1],
                              plo[2 * ks + 1][0], plo[2 * ks + 1][1]};
            #pragma unroll
            for (int jp = 0; jp < 4; jp++) {
                uint32_t vh[4], vl[4];
                uint32_t boff = bVbase + (uint32_t)(ks * 16 * RS + jp * 32);
                ldsm_x4t(vh, smb + OFF_VHI + boff);
                ldsm_x4t(vl, smb + OFF_VLO + boff);
                mma16816(oacc[2 * jp],     ah, vh);
                mma16816(oacc[2 * jp + 1], ah, vh + 2);
                mma16816(oacc[2 * jp],     ah, vl);
                mma16816(oacc[2 * jp + 1], ah, vl + 2);
                mma16816(oacc[2 * jp],     al, vh);
                mma16816(oacc[2 * jp + 1], al, vh + 2);
            }
        }
    }

    // ---- reduce row sums within quads, normalize O, write context ----
    lsum0 += __shfl_xor_sync(0xffffffffu, lsum0, 1);
    lsum0 += __shfl_xor_sync(0xffffffffu, lsum0, 2);
    lsum1 += __shfl_xor_sync(0xffffffffu, lsum1, 1);
    lsum1 += __shfl_xor_sync(0xffffffffu, lsum1, 2);
    if (q == 0) {
        g_lsum[bh * S_LEN + grow0]     = lsum0;
        g_lsum[bh * S_LEN + grow0 + 8] = lsum1;
    }
    const float inv0 = 1.f / lsum0;
    const float inv1 = 1.f / lsum1;
    #pragma unroll
    for (int j = 0; j < 8; j++) {
        int cj = j * 8 + q * 2;
        *(float2*)(ctx + (size_t)grow0 * DK + cj) =
            make_float2(oacc[j][0] * inv0, oacc[j][1] * inv0);
        *(float2*)(ctx + (size_t)(grow0 + 8) * DK + cj) =
            make_float2(oacc[j][2] * inv1, oacc[j][3] * inv1);
    }
}

// ---------------------------------------------------------------------------
// Pass 2: attn[row, col<=row] *= 1/l(row); attn[row, col>row] = 0.
// ---------------------------------------------------------------------------
__global__ __launch_bounds__(256)
void attn_pass2(float* __restrict__ out)
{
    const int gid = blockIdx.x;               // bh*S_LEN + row
    const int r   = gid & (S_LEN - 1);
    const float inv = 1.f / g_lsum[gid];
    float4* rowp = (float4*)(out + CTX_ELEMS + (size_t)gid * S_LEN);
    const int tid = threadIdx.x;

    #pragma unroll
    for (int it = 0; it < 2; it++) {
        int c4  = tid + it * 256;
        int col = c4 << 2;
        float4 v;
        if (col + 3 <= r) {
            v = rowp[c4];
            v.x *= inv; v.y *= inv; v.z *= inv; v.w *= inv;
        } else if (col > r) {
            v.x = 0.f; v.y = 0.f; v.z = 0.f; v.w = 0.f;
        } else {
            v = rowp[c4];
            v.x = (col + 0 <= r) ? v.x * inv : 0.f;
            v.y = (col + 1 <= r) ? v.y * inv : 0.f;
            v.z = (col + 2 <= r) ? v.z * inv : 0.f;
            v.w = (col + 3 <= r) ? v.w * inv : 0.f;
        }
        rowp[c4] = v;
    }
}

extern "C" void kernel_launch(void* const* d_in, const int* in_sizes, int n_in,
                              void* d_out, int out_size)
{
    const float* Q = (const float*)d_in[0];
    const float* K = (const float*)d_in[1];
    const float* V = (const float*)d_in[2];
    float* out = (float*)d_out;

    cudaFuncSetAttribute(attn_pass1, cudaFuncAttributeMaxDynamicSharedMemorySize,
                         SMEM_TOTAL);

    dim3 grid1(S_LEN / BM, NBH);
    attn_pass1<<<grid1, 256, SMEM_TOTAL>>>(Q, K, V, out);
    attn_pass2<<<NBH * S_LEN, 256>>>(out);
}